// round 3
// baseline (speedup 1.0000x reference)
#include <cuda_runtime.h>

#define W 512
#define H 512
#define PADR 3
#define NPLANES 96
#define ROWS_PER_SLAB 64
#define SLABS 8            // ceil(506 / 64)
#define TPB 128
#define SBUF 520           // 4 pad + 512 + 4 pad

__device__ double g_acc;

__global__ void zero_acc_kernel() { g_acc = 0.0; }

__global__ void finalize_kernel(float* out) {
    out[0] = (float)(g_acc * (1.0 / (96.0 * 506.0 * 506.0)));
}

// Horizontal sliding 7-sum: smem base s, thread's 4 outputs at columns xb..xb+3
// (smem index = column + 4). Reads indices xb .. xb+10.
__device__ __forceinline__ void horiz7(const float* __restrict__ s, int xb, float o[4]) {
    float4 a = *(const float4*)(s + xb);
    float4 b = *(const float4*)(s + xb + 4);
    float4 c = *(const float4*)(s + xb + 8);
    float t = a.y + a.z + a.w + b.x + b.y + b.z + b.w;  // cols x-3..x+3 for x = xb
    o[0] = t;
    t += c.x - a.y; o[1] = t;
    t += c.y - a.z; o[2] = t;
    t += c.z - a.w; o[3] = t;
}

__global__ __launch_bounds__(TPB) void ssim_main(const float* __restrict__ g1,
                                                 const float* __restrict__ g2) {
    // Double-buffered: one barrier per row instead of two.
    __shared__ float sSx[2][SBUF], sSy[2][SBUF], sSw[2][SBUF], sSxy[2][SBUF];
    __shared__ float wsum[TPB / 32];

    const int t     = threadIdx.x;
    const int plane = blockIdx.x / SLABS;
    const int slab  = blockIdx.x % SLABS;
    const int y0    = PADR + slab * ROWS_PER_SLAB;
    const int y1    = min(y0 + ROWS_PER_SLAB - 1, H - 1 - PADR);   // <= 508
    const int xb    = t * 4;

    const float* p1 = g1 + (size_t)plane * (W * H);
    const float* p2 = g2 + (size_t)plane * (W * H);

    // zero the halo pads once (visible after the first in-loop barrier)
    if (t < 8) {
        int pb = t >> 2;            // buffer 0/1
        int k  = t & 3;             // pad lane
        sSx[pb][k] = 0.f;  sSy[pb][k] = 0.f;  sSw[pb][k] = 0.f;  sSxy[pb][k] = 0.f;
        sSx[pb][516 + k] = 0.f; sSy[pb][516 + k] = 0.f;
        sSw[pb][516 + k] = 0.f; sSxy[pb][516 + k] = 0.f;
    }

    // Vertical running sums over rows y-3..y+3 for this thread's 4 columns.
    float Vx[4] = {0,0,0,0}, Vy[4] = {0,0,0,0}, Vw[4] = {0,0,0,0}, Vxy[4] = {0,0,0,0};

    #pragma unroll
    for (int j = -PADR; j <= PADR; j++) {
        float4 A = *(const float4*)(p1 + (y0 + j) * W + xb);
        float4 B = *(const float4*)(p2 + (y0 + j) * W + xb);
        float a[4] = {A.x, A.y, A.z, A.w};
        float b[4] = {B.x, B.y, B.z, B.w};
        #pragma unroll
        for (int i = 0; i < 4; i++) {
            Vx[i] += a[i];
            Vy[i] += b[i];
            Vw[i]  = fmaf(a[i], a[i], Vw[i]);
            Vw[i]  = fmaf(b[i], b[i], Vw[i]);
            Vxy[i] = fmaf(a[i], b[i], Vxy[i]);
        }
    }

    // Unnormalized-sum constants: 49^2 folded in, only (A1*A2)/(B1*B2) matters.
    const float c1s = 0.2401f;            // (0.01)^2 * 49^2
    const float c2s = 2.1609f;            // (0.03)^2 * 49^2
    const float CN  = 49.0f / 48.0f;      // CONV_NORM
    const float K2  = 2.0f * CN;
    const float FK  = 49.0f * K2;
    const float M49 = 49.0f * CN;

    float acc = 0.f;

    for (int y = y0;; y++) {
        const int pb = y & 1;
        // Safe w.r.t. prior reads of this buffer: those happened in iteration
        // y-2, and every thread passed iteration y-1's barrier since then.
        *(float4*)(sSx[pb]  + 4 + xb) = make_float4(Vx[0],  Vx[1],  Vx[2],  Vx[3]);
        *(float4*)(sSy[pb]  + 4 + xb) = make_float4(Vy[0],  Vy[1],  Vy[2],  Vy[3]);
        *(float4*)(sSw[pb]  + 4 + xb) = make_float4(Vw[0],  Vw[1],  Vw[2],  Vw[3]);
        *(float4*)(sSxy[pb] + 4 + xb) = make_float4(Vxy[0], Vxy[1], Vxy[2], Vxy[3]);
        __syncthreads();

        float Sx[4], Sy[4], Sw[4], Sxy[4];
        horiz7(sSx[pb],  xb, Sx);
        horiz7(sSy[pb],  xb, Sy);
        horiz7(sSw[pb],  xb, Sw);
        horiz7(sSxy[pb], xb, Sxy);

        #pragma unroll
        for (int i = 0; i < 4; i++) {
            int x = xb + i;
            if (x >= PADR && x <= W - 1 - PADR) {
                float P  = Sx[i] * Sy[i];
                float r  = fmaf(Sx[i], Sx[i], Sy[i] * Sy[i]);
                float A1 = fmaf(P, 2.0f, c1s);
                float A2 = fmaf(-K2, P, fmaf(Sxy[i], FK, c2s));
                float B1 = r + c1s;
                float B2 = fmaf(-CN, r, fmaf(Sw[i], M49, c2s));
                acc += __fdividef(A1 * A2, B1 * B2);
            }
        }

        if (y >= y1) break;

        // slide: add row y+4, subtract row y-3 (y-3 re-read; hot in L1)
        float4 A  = *(const float4*)(p1 + (y + 4) * W + xb);
        float4 B  = *(const float4*)(p2 + (y + 4) * W + xb);
        float4 Ao = *(const float4*)(p1 + (y - 3) * W + xb);
        float4 Bo = *(const float4*)(p2 + (y - 3) * W + xb);
        float a[4]  = {A.x,  A.y,  A.z,  A.w};
        float b[4]  = {B.x,  B.y,  B.z,  B.w};
        float ao[4] = {Ao.x, Ao.y, Ao.z, Ao.w};
        float bo[4] = {Bo.x, Bo.y, Bo.z, Bo.w};
        #pragma unroll
        for (int i = 0; i < 4; i++) {
            Vx[i] += a[i] - ao[i];
            Vy[i] += b[i] - bo[i];
            Vw[i]  = fmaf(a[i],  a[i],  Vw[i]);
            Vw[i]  = fmaf(b[i],  b[i],  Vw[i]);
            Vw[i]  = fmaf(-ao[i], ao[i], Vw[i]);
            Vw[i]  = fmaf(-bo[i], bo[i], Vw[i]);
            Vxy[i] = fmaf(a[i],  b[i],  Vxy[i]);
            Vxy[i] = fmaf(-ao[i], bo[i], Vxy[i]);
        }
    }

    // Block reduction -> global double accumulator
    #pragma unroll
    for (int off = 16; off; off >>= 1)
        acc += __shfl_down_sync(0xffffffffu, acc, off);
    if ((t & 31) == 0) wsum[t >> 5] = acc;
    __syncthreads();
    if (t == 0) {
        float s = 0.f;
        #pragma unroll
        for (int i = 0; i < TPB / 32; i++) s += wsum[i];
        atomicAdd(&g_acc, (double)s);
    }
}

extern "C" void kernel_launch(void* const* d_in, const int* in_sizes, int n_in,
                              void* d_out, int out_size) {
    (void)in_sizes; (void)n_in; (void)out_size;
    const float* img1 = (const float*)d_in[0];
    const float* img2 = (const float*)d_in[1];
    zero_acc_kernel<<<1, 1>>>();
    ssim_main<<<NPLANES * SLABS, TPB>>>(img1, img2);
    finalize_kernel<<<1, 1>>>((float*)d_out);
}

// round 4
// speedup vs baseline: 1.0459x; 1.0459x over previous
#include <cuda_runtime.h>

#define W 512
#define H 512
#define PADR 3
#define NPLANES 96
#define ROWS_PER_SLAB 64
#define SLABS 8            // ceil(506 / 64)
#define TPB 128
#define SBUF 520           // 4 pad + 512 + 4 pad
#define NBLK (NPLANES * SLABS)

typedef unsigned long long u64;

__device__ float    g_part[NBLK];
__device__ unsigned g_count = 0;   // self-resetting; safe across graph replays

// ---- packed f32x2 helpers (Blackwell; ptxas never auto-fuses these) ----
__device__ __forceinline__ u64 pk(float lo, float hi) {
    u64 r; asm("mov.b64 %0, {%1, %2};" : "=l"(r) : "f"(lo), "f"(hi)); return r;
}
__device__ __forceinline__ void upk(u64 v, float& lo, float& hi) {
    asm("mov.b64 {%0, %1}, %2;" : "=f"(lo), "=f"(hi) : "l"(v));
}
__device__ __forceinline__ u64 add2(u64 a, u64 b) {
    u64 r; asm("add.rn.f32x2 %0, %1, %2;" : "=l"(r) : "l"(a), "l"(b)); return r;
}
__device__ __forceinline__ u64 mul2(u64 a, u64 b) {
    u64 r; asm("mul.rn.f32x2 %0, %1, %2;" : "=l"(r) : "l"(a), "l"(b)); return r;
}
__device__ __forceinline__ u64 fma2(u64 a, u64 b, u64 c) {
    u64 r; asm("fma.rn.f32x2 %0, %1, %2, %3;" : "=l"(r) : "l"(a), "l"(b), "l"(c)); return r;
}

// Horizontal sliding 7-sum: smem base s (16B aligned), outputs for cols xb..xb+3
// (smem index = column + 4). Reads indices xb .. xb+10.
__device__ __forceinline__ void horiz7(const float* __restrict__ s, int xb, float o[4]) {
    float4 a = *(const float4*)(s + xb);
    float4 b = *(const float4*)(s + xb + 4);
    float4 c = *(const float4*)(s + xb + 8);
    float t = a.y + a.z + a.w + b.x + b.y + b.z + b.w;
    o[0] = t;
    t += c.x - a.y; o[1] = t;
    t += c.y - a.z; o[2] = t;
    t += c.z - a.w; o[3] = t;
}

__global__ __launch_bounds__(TPB) void ssim_main(const float* __restrict__ g1,
                                                 const float* __restrict__ g2,
                                                 float* __restrict__ out) {
    __shared__ __align__(16) float sSx[2][SBUF], sSy[2][SBUF], sSw[2][SBUF], sSxy[2][SBUF];
    __shared__ float  wsum[TPB / 32];
    __shared__ bool   isLast;
    __shared__ double dsum[TPB];

    const int t     = threadIdx.x;
    const int bid   = blockIdx.x;
    const int plane = bid / SLABS;
    const int slab  = bid % SLABS;
    const int y0    = PADR + slab * ROWS_PER_SLAB;
    const int y1    = min(y0 + ROWS_PER_SLAB - 1, H - 1 - PADR);   // <= 508
    const int xb    = t * 4;

    const float* p1 = g1 + (size_t)plane * (W * H);
    const float* p2 = g2 + (size_t)plane * (W * H);

    // zero halo pads once (both buffers); visible after first in-loop barrier
    if (t < 8) {
        int pb = t >> 2, k = t & 3;
        sSx[pb][k] = 0.f;  sSy[pb][k] = 0.f;  sSw[pb][k] = 0.f;  sSxy[pb][k] = 0.f;
        sSx[pb][516 + k] = 0.f; sSy[pb][516 + k] = 0.f;
        sSw[pb][516 + k] = 0.f; sSxy[pb][516 + k] = 0.f;
    }

    // Vertical running sums (rows y-3..y+3), packed 2 cols per u64.
    u64 Vx0 = 0, Vx1 = 0, Vy0 = 0, Vy1 = 0, Vw0 = 0, Vw1 = 0, Vxy0 = 0, Vxy1 = 0;

    #pragma unroll
    for (int j = -PADR; j <= PADR; j++) {
        float4 A = *(const float4*)(p1 + (y0 + j) * W + xb);
        float4 B = *(const float4*)(p2 + (y0 + j) * W + xb);
        u64 aL = pk(A.x, A.y), aH = pk(A.z, A.w);
        u64 bL = pk(B.x, B.y), bH = pk(B.z, B.w);
        Vx0 = add2(Vx0, aL);  Vx1 = add2(Vx1, aH);
        Vy0 = add2(Vy0, bL);  Vy1 = add2(Vy1, bH);
        Vw0 = fma2(aL, aL, Vw0); Vw0 = fma2(bL, bL, Vw0);
        Vw1 = fma2(aH, aH, Vw1); Vw1 = fma2(bH, bH, Vw1);
        Vxy0 = fma2(aL, bL, Vxy0); Vxy1 = fma2(aH, bH, Vxy1);
    }

    // Unnormalized-sum constants (49^2 folded in; ratio invariant).
    const float c1s = 0.2401f, c2s = 2.1609f;
    const float CN = 49.0f / 48.0f;
    const u64 M1   = pk(-1.f, -1.f);
    const u64 TWO2 = pk(2.f, 2.f);
    const u64 C1v  = pk(c1s, c1s);
    const u64 C2v  = pk(c2s, c2s);
    const u64 MK2v = pk(-2.f * CN, -2.f * CN);
    const u64 FKv  = pk(98.f * CN, 98.f * CN);
    const u64 MCNv = pk(-CN, -CN);
    const u64 M49v = pk(49.f * CN, 49.f * CN);

    float acc = 0.f;

    for (int y = y0;; y++) {
        const int pb = y & 1;
        // Prior reads of this buffer were in iteration y-2; iteration y-1's
        // barrier separates them from this write.
        *(ulonglong2*)(sSx[pb]  + 4 + xb) = make_ulonglong2(Vx0,  Vx1);
        *(ulonglong2*)(sSy[pb]  + 4 + xb) = make_ulonglong2(Vy0,  Vy1);
        *(ulonglong2*)(sSw[pb]  + 4 + xb) = make_ulonglong2(Vw0,  Vw1);
        *(ulonglong2*)(sSxy[pb] + 4 + xb) = make_ulonglong2(Vxy0, Vxy1);
        __syncthreads();

        float Sx[4], Sy[4], Sw[4], Sxy[4];
        horiz7(sSx[pb],  xb, Sx);
        horiz7(sSy[pb],  xb, Sy);
        horiz7(sSw[pb],  xb, Sw);
        horiz7(sSxy[pb], xb, Sxy);

        // Packed SSIM map (2 cols per op)
        u64 sx0 = pk(Sx[0],  Sx[1]),  sx1 = pk(Sx[2],  Sx[3]);
        u64 sy0 = pk(Sy[0],  Sy[1]),  sy1 = pk(Sy[2],  Sy[3]);
        u64 sw0 = pk(Sw[0],  Sw[1]),  sw1 = pk(Sw[2],  Sw[3]);
        u64 sp0 = pk(Sxy[0], Sxy[1]), sp1 = pk(Sxy[2], Sxy[3]);

        u64 P0 = mul2(sx0, sy0),            P1 = mul2(sx1, sy1);
        u64 r0 = fma2(sx0, sx0, mul2(sy0, sy0));
        u64 r1 = fma2(sx1, sx1, mul2(sy1, sy1));
        u64 A10 = fma2(P0, TWO2, C1v),      A11 = fma2(P1, TWO2, C1v);
        u64 A20 = fma2(MK2v, P0, fma2(sp0, FKv, C2v));
        u64 A21 = fma2(MK2v, P1, fma2(sp1, FKv, C2v));
        u64 B10 = add2(r0, C1v),            B11 = add2(r1, C1v);
        u64 B20 = fma2(MCNv, r0, fma2(sw0, M49v, C2v));
        u64 B21 = fma2(MCNv, r1, fma2(sw1, M49v, C2v));
        u64 nm0 = mul2(A10, A20),           nm1 = mul2(A11, A21);
        u64 dn0 = mul2(B10, B20),           dn1 = mul2(B11, B21);

        float n0, n1, n2, n3, d0, d1, d2, d3;
        upk(nm0, n0, n1); upk(nm1, n2, n3);
        upk(dn0, d0, d1); upk(dn1, d2, d3);
        // denominators are strictly positive (Cauchy-Schwarz) -> safe to divide
        float v0 = __fdividef(n0, d0), v1 = __fdividef(n1, d1);
        float v2 = __fdividef(n2, d2), v3 = __fdividef(n3, d3);
        if (t == 0)            acc += v3;                    // only x=3 valid
        else if (t == TPB - 1) acc += v0;                    // only x=508 valid
        else                   acc += (v0 + v1) + (v2 + v3);

        if (y >= y1) break;

        // slide: add row y+4, subtract row y-3 (re-read; hot in L1)
        float4 A  = *(const float4*)(p1 + (y + 4) * W + xb);
        float4 B  = *(const float4*)(p2 + (y + 4) * W + xb);
        float4 Ao = *(const float4*)(p1 + (y - 3) * W + xb);
        float4 Bo = *(const float4*)(p2 + (y - 3) * W + xb);
        u64 aL  = pk(A.x,  A.y),  aH  = pk(A.z,  A.w);
        u64 bL  = pk(B.x,  B.y),  bH  = pk(B.z,  B.w);
        u64 aoL = pk(Ao.x, Ao.y), aoH = pk(Ao.z, Ao.w);
        u64 boL = pk(Bo.x, Bo.y), boH = pk(Bo.z, Bo.w);
        u64 naL = mul2(aoL, M1), naH = mul2(aoH, M1);
        u64 nbL = mul2(boL, M1), nbH = mul2(boH, M1);
        Vx0 = add2(Vx0, add2(aL, naL));  Vx1 = add2(Vx1, add2(aH, naH));
        Vy0 = add2(Vy0, add2(bL, nbL));  Vy1 = add2(Vy1, add2(bH, nbH));
        Vw0 = fma2(aL, aL, fma2(bL, bL, fma2(naL, aoL, fma2(nbL, boL, Vw0))));
        Vw1 = fma2(aH, aH, fma2(bH, bH, fma2(naH, aoH, fma2(nbH, boH, Vw1))));
        Vxy0 = fma2(aL, bL, fma2(naL, boL, Vxy0));
        Vxy1 = fma2(aH, bH, fma2(naH, boH, Vxy1));
    }

    // Block reduction (deterministic)
    #pragma unroll
    for (int off = 16; off; off >>= 1)
        acc += __shfl_down_sync(0xffffffffu, acc, off);
    if ((t & 31) == 0) wsum[t >> 5] = acc;
    __syncthreads();

    if (t == 0) {
        float s = 0.f;
        #pragma unroll
        for (int i = 0; i < TPB / 32; i++) s += wsum[i];
        g_part[bid] = s;
        __threadfence();
        unsigned old = atomicAdd(&g_count, 1u);
        isLast = (old == NBLK - 1);
    }
    __syncthreads();

    // Last block reduces all partials (fixed order -> deterministic)
    if (isLast) {
        __threadfence();
        double s = 0.0;
        for (int i = t; i < NBLK; i += TPB) s += (double)g_part[i];
        dsum[t] = s;
        __syncthreads();
        #pragma unroll
        for (int o = TPB / 2; o > 0; o >>= 1) {
            if (t < o) dsum[t] += dsum[t + o];
            __syncthreads();
        }
        if (t == 0) {
            out[0] = (float)(dsum[0] * (1.0 / (96.0 * 506.0 * 506.0)));
            g_count = 0;   // reset for next graph replay
        }
    }
}

extern "C" void kernel_launch(void* const* d_in, const int* in_sizes, int n_in,
                              void* d_out, int out_size) {
    (void)in_sizes; (void)n_in; (void)out_size;
    const float* img1 = (const float*)d_in[0];
    const float* img2 = (const float*)d_in[1];
    ssim_main<<<NBLK, TPB>>>(img1, img2, (float*)d_out);
}

// round 5
// speedup vs baseline: 1.2172x; 1.1638x over previous
#include <cuda_runtime.h>

#define W 512
#define H 512
#define NPLANES 96
#define ROWS_PER_SLAB 32
#define SLABS 16           // 16*32 = 512 >= 506
#define TPB 64             // 2 warps; thread owns 8 columns
#define NBLK (NPLANES * SLABS)

typedef unsigned long long u64;

__device__ float    g_part[NBLK];
__device__ unsigned g_count = 0;   // self-resetting; safe across graph replays

// ---- packed f32x2 helpers (ptxas never auto-fuses these) ----
__device__ __forceinline__ u64 pk(float lo, float hi) {
    u64 r; asm("mov.b64 %0, {%1, %2};" : "=l"(r) : "f"(lo), "f"(hi)); return r;
}
__device__ __forceinline__ void upk(u64 v, float& lo, float& hi) {
    asm("mov.b64 {%0, %1}, %2;" : "=f"(lo), "=f"(hi) : "l"(v));
}
__device__ __forceinline__ u64 add2(u64 a, u64 b) {
    u64 r; asm("add.rn.f32x2 %0, %1, %2;" : "=l"(r) : "l"(a), "l"(b)); return r;
}
__device__ __forceinline__ u64 mul2(u64 a, u64 b) {
    u64 r; asm("mul.rn.f32x2 %0, %1, %2;" : "=l"(r) : "l"(a), "l"(b)); return r;
}
__device__ __forceinline__ u64 fma2(u64 a, u64 b, u64 c) {
    u64 r; asm("fma.rn.f32x2 %0, %1, %2, %3;" : "=l"(r) : "l"(a), "l"(b), "l"(c)); return r;
}

__global__ __launch_bounds__(TPB, 9) void ssim_main(const float* __restrict__ g1,
                                                    const float* __restrict__ g2,
                                                    float* __restrict__ out) {
    // tiny warp-boundary exchange (double-buffered) + reduction scratch
    __shared__ float  exL[2][4][3];   // written by t=31 (suffix sums), read by t=32
    __shared__ float  exR[2][4][3];   // written by t=32 (prefix sums),  read by t=31
    __shared__ float  wsum[2];
    __shared__ bool   isLast;
    __shared__ double dsum[TPB];

    const int t     = threadIdx.x;
    const int lane  = t & 31;
    const int bid   = blockIdx.x;
    const int plane = bid / SLABS;
    const int slab  = bid % SLABS;
    const int y0    = 3 + slab * ROWS_PER_SLAB;
    const int y1    = min(y0 + ROWS_PER_SLAB - 1, 508);
    const int xb    = t * 8;                 // 8 columns per thread, 32B aligned

    const float* p1 = g1 + (size_t)plane * (W * H);
    const float* p2 = g2 + (size_t)plane * (W * H);

    // Vertical running sums over rows y-3..y+3: 4 quantities x 4 col-pairs.
    // q: 0=Sx, 1=Sy, 2=Sxx+Syy, 3=Sxy
    u64 V[4][4];
    #pragma unroll
    for (int q = 0; q < 4; q++)
        #pragma unroll
        for (int j = 0; j < 4; j++) V[q][j] = 0;

    #pragma unroll
    for (int j = -3; j <= 3; j++) {
        const float* r1 = p1 + (y0 + j) * W + xb;
        const float* r2 = p2 + (y0 + j) * W + xb;
        float4 A0 = *(const float4*)r1,       A1 = *(const float4*)(r1 + 4);
        float4 B0 = *(const float4*)r2,       B1 = *(const float4*)(r2 + 4);
        u64 a[4] = {pk(A0.x, A0.y), pk(A0.z, A0.w), pk(A1.x, A1.y), pk(A1.z, A1.w)};
        u64 b[4] = {pk(B0.x, B0.y), pk(B0.z, B0.w), pk(B1.x, B1.y), pk(B1.z, B1.w)};
        #pragma unroll
        for (int jj = 0; jj < 4; jj++) {
            V[0][jj] = add2(V[0][jj], a[jj]);
            V[1][jj] = add2(V[1][jj], b[jj]);
            V[2][jj] = fma2(a[jj], a[jj], fma2(b[jj], b[jj], V[2][jj]));
            V[3][jj] = fma2(a[jj], b[jj], V[3][jj]);
        }
    }

    // Unnormalized-sum constants (49^2 folded in; ratio invariant).
    const float c1s = 0.2401f, c2s = 2.1609f;
    const float CN  = 49.0f / 48.0f;
    const u64 M1   = pk(-1.f, -1.f);
    const u64 TWO2 = pk(2.f, 2.f);
    const u64 C1v  = pk(c1s, c1s);
    const u64 C2v  = pk(c2s, c2s);
    const u64 MK2v = pk(-2.f * CN, -2.f * CN);
    const u64 FKv  = pk(98.f * CN, 98.f * CN);
    const u64 MCNv = pk(-CN, -CN);
    const u64 M49v = pk(49.f * CN, 49.f * CN);

    float acc = 0.f;

    for (int y = y0;; y++) {
        const int pb = y & 1;

        // Warp-boundary exchange (col 256): t=31 provides its last-3 suffix
        // sums to t=32; t=32 provides its first-3 prefix sums to t=31.
        if (t == 31) {
            #pragma unroll
            for (int q = 0; q < 4; q++) {
                float v4, v5, v6, v7;
                upk(V[q][2], v4, v5); upk(V[q][3], v6, v7);
                float s3 = v7, s2 = v6 + v7, s1 = v5 + s2;
                exL[pb][q][0] = s1; exL[pb][q][1] = s2; exL[pb][q][2] = s3;
            }
        }
        if (t == 32) {
            #pragma unroll
            for (int q = 0; q < 4; q++) {
                float v0, v1, v2, v3;
                upk(V[q][0], v0, v1); upk(V[q][1], v2, v3);
                exR[pb][q][0] = v0; exR[pb][q][1] = v0 + v1; exR[pb][q][2] = v0 + v1 + v2;
            }
        }
        __syncthreads();

        // Horizontal 7-window sums for 8 output cols via prefix + shuffles.
        u64 Wq[4][4];
        #pragma unroll
        for (int q = 0; q < 4; q++) {
            float v0, v1, v2, v3, v4, v5, v6, v7;
            upk(V[q][0], v0, v1); upk(V[q][1], v2, v3);
            upk(V[q][2], v4, v5); upk(V[q][3], v6, v7);
            float f0 = v0;
            float f1 = f0 + v1, f2 = f1 + v2, f3 = f2 + v3;
            float f4 = f3 + v4, f5 = f4 + v5, f6 = f5 + v6, f7 = f6 + v7;
            float s1 = f7 - f4, s2 = f7 - f5, s3 = f7 - f6;

            float sL1 = __shfl_up_sync(0xffffffffu, s1, 1);
            float sL2 = __shfl_up_sync(0xffffffffu, s2, 1);
            float sL3 = __shfl_up_sync(0xffffffffu, s3, 1);
            float pR0 = __shfl_down_sync(0xffffffffu, f0, 1);
            float pR1 = __shfl_down_sync(0xffffffffu, f1, 1);
            float pR2 = __shfl_down_sync(0xffffffffu, f2, 1);
            if (lane == 0 && t != 0) {           // t=32: real left halo from t=31
                sL1 = exL[pb][q][0]; sL2 = exL[pb][q][1]; sL3 = exL[pb][q][2];
            }
            if (lane == 31 && t != TPB - 1) {    // t=31: real right halo from t=32
                pR0 = exR[pb][q][0]; pR1 = exR[pb][q][1]; pR2 = exR[pb][q][2];
            }
            float w0 = sL1 + f3;
            float w1 = sL2 + f4;
            float w2 = sL3 + f5;
            float w3 = f6;
            float w4 = f7 - f0;
            float w5 = (f7 - f1) + pR0;
            float w6 = (f7 - f2) + pR1;
            float w7 = (f7 - f3) + pR2;
            Wq[q][0] = pk(w0, w1); Wq[q][1] = pk(w2, w3);
            Wq[q][2] = pk(w4, w5); Wq[q][3] = pk(w6, w7);
        }

        // Packed SSIM map for 4 col-pairs.
        float v[8];
        #pragma unroll
        for (int p = 0; p < 4; p++) {
            u64 sx = Wq[0][p], sy = Wq[1][p], sw = Wq[2][p], sp = Wq[3][p];
            u64 P  = mul2(sx, sy);
            u64 r  = fma2(sx, sx, mul2(sy, sy));
            u64 A1v = fma2(P, TWO2, C1v);
            u64 A2v = fma2(MK2v, P, fma2(sp, FKv, C2v));
            u64 B1v = add2(r, C1v);
            u64 B2v = fma2(MCNv, r, fma2(sw, M49v, C2v));
            u64 nm = mul2(A1v, A2v), dn = mul2(B1v, B2v);
            float n0, n1, d0, d1;
            upk(nm, n0, n1); upk(dn, d0, d1);
            v[2 * p]     = __fdividef(n0, d0);
            v[2 * p + 1] = __fdividef(n1, d1);
        }
        // interior columns are 3..508: t=0 drops k<3, t=63 drops k>4
        if (t == 0)            acc += ((v[3] + v[4]) + (v[5] + v[6])) + v[7];
        else if (t == TPB - 1) acc += ((v[0] + v[1]) + (v[2] + v[3])) + v[4];
        else                   acc += ((v[0] + v[1]) + (v[2] + v[3]))
                                    + ((v[4] + v[5]) + (v[6] + v[7]));

        if (y >= y1) break;

        // Slide vertical sums: add row y+4, subtract row y-3 (re-read, hot in cache)
        const float* rn1 = p1 + (y + 4) * W + xb;
        const float* rn2 = p2 + (y + 4) * W + xb;
        const float* ro1 = p1 + (y - 3) * W + xb;
        const float* ro2 = p2 + (y - 3) * W + xb;
        float4 A0 = *(const float4*)rn1,  A1 = *(const float4*)(rn1 + 4);
        float4 B0 = *(const float4*)rn2,  B1 = *(const float4*)(rn2 + 4);
        float4 C0 = *(const float4*)ro1,  C1f = *(const float4*)(ro1 + 4);
        float4 D0 = *(const float4*)ro2,  D1 = *(const float4*)(ro2 + 4);
        u64 a[4]  = {pk(A0.x, A0.y), pk(A0.z, A0.w), pk(A1.x, A1.y), pk(A1.z, A1.w)};
        u64 b[4]  = {pk(B0.x, B0.y), pk(B0.z, B0.w), pk(B1.x, B1.y), pk(B1.z, B1.w)};
        u64 ao[4] = {pk(C0.x, C0.y), pk(C0.z, C0.w), pk(C1f.x, C1f.y), pk(C1f.z, C1f.w)};
        u64 bo[4] = {pk(D0.x, D0.y), pk(D0.z, D0.w), pk(D1.x, D1.y), pk(D1.z, D1.w)};
        #pragma unroll
        for (int jj = 0; jj < 4; jj++) {
            u64 na = mul2(ao[jj], M1), nb = mul2(bo[jj], M1);
            V[0][jj] = add2(V[0][jj], add2(a[jj], na));
            V[1][jj] = add2(V[1][jj], add2(b[jj], nb));
            V[2][jj] = fma2(a[jj], a[jj], fma2(b[jj], b[jj],
                        fma2(na, ao[jj], fma2(nb, bo[jj], V[2][jj]))));
            V[3][jj] = fma2(a[jj], b[jj], fma2(na, bo[jj], V[3][jj]));
        }
    }

    // Block reduction (deterministic)
    #pragma unroll
    for (int off = 16; off; off >>= 1)
        acc += __shfl_down_sync(0xffffffffu, acc, off);
    if (lane == 0) wsum[t >> 5] = acc;
    __syncthreads();

    if (t == 0) {
        g_part[bid] = wsum[0] + wsum[1];
        __threadfence();
        unsigned old = atomicAdd(&g_count, 1u);
        isLast = (old == NBLK - 1);
    }
    __syncthreads();

    // Last block reduces all partials (fixed order -> deterministic)
    if (isLast) {
        __threadfence();
        double s = 0.0;
        for (int i = t; i < NBLK; i += TPB) s += (double)g_part[i];
        dsum[t] = s;
        __syncthreads();
        #pragma unroll
        for (int o = TPB / 2; o > 0; o >>= 1) {
            if (t < o) dsum[t] += dsum[t + o];
            __syncthreads();
        }
        if (t == 0) {
            out[0] = (float)(dsum[0] * (1.0 / (96.0 * 506.0 * 506.0)));
            g_count = 0;   // reset for next graph replay
        }
    }
}

extern "C" void kernel_launch(void* const* d_in, const int* in_sizes, int n_in,
                              void* d_out, int out_size) {
    (void)in_sizes; (void)n_in; (void)out_size;
    const float* img1 = (const float*)d_in[0];
    const float* img2 = (const float*)d_in[1];
    ssim_main<<<NBLK, TPB>>>(img1, img2, (float*)d_out);
}